// round 1
// baseline (speedup 1.0000x reference)
#include <cuda_runtime.h>

#define NMAX 50000
#define EMAX 800000
#define FIN 128
#define NHEAD 4
#define HF 256   // NHEAD * F_OUT

// ---- scratch (device globals; no allocation allowed) ----
__device__ float    d_ft[NMAX * HF];      // projected features [N,256]
__device__ float    d_e[EMAX * NHEAD];    // edge scores [E,4]
__device__ unsigned d_m[NMAX * NHEAD];    // per-dst max (ordered-uint encoding)
__device__ float    d_denom[NMAX * NHEAD];
__device__ float    d_el2[NMAX * NHEAD];
__device__ float    d_er2[NMAX * NHEAD];
__device__ float    d_w[NHEAD * FIN];     // al*ar - 2*al1*ar1
__device__ float    d_wl1[NHEAD * FIN];   // al1^2
__device__ float    d_wr1[NHEAD * FIN];   // ar1^2

// monotone float<->uint mapping so atomicMax(unsigned) == float max
__device__ __forceinline__ unsigned fOrd(float f) {
    unsigned u = __float_as_uint(f);
    return (u & 0x80000000u) ? ~u : (u | 0x80000000u);
}
__device__ __forceinline__ float fUnord(unsigned u) {
    return (u & 0x80000000u) ? __uint_as_float(u & 0x7FFFFFFFu)
                             : __uint_as_float(~u);
}

__device__ __forceinline__ float sel4(const float a[4], int l) {
    return l == 0 ? a[0] : l == 1 ? a[1] : l == 2 ? a[2] : a[3];
}

// ---- K0: combine attention vectors ----
__global__ void k0_prep(const float* __restrict__ al, const float* __restrict__ ar,
                        const float* __restrict__ al1, const float* __restrict__ ar1) {
    int i = threadIdx.x;  // 512 threads
    d_w[i]   = al[i] * ar[i] - 2.0f * al1[i] * ar1[i];
    d_wl1[i] = al1[i] * al1[i];
    d_wr1[i] = ar1[i] * ar1[i];
}

// ---- Kz: zero output accumulator ----
__global__ void kzero(float4* __restrict__ out, int total4) {
    int i = blockIdx.x * blockDim.x + threadIdx.x;
    if (i < total4) out[i] = make_float4(0.f, 0.f, 0.f, 0.f);
}

// ---- K2: per-node el2/er2 + init m/denom. One warp per node. ----
__global__ void k2_node(const float* __restrict__ feat, int n) {
    __shared__ float wl[NHEAD * FIN], wr[NHEAD * FIN];
    int t = threadIdx.x;
    wl[t] = d_wl1[t]; wl[t + 256] = d_wl1[t + 256];
    wr[t] = d_wr1[t]; wr[t + 256] = d_wr1[t + 256];
    __syncthreads();
    int warp = t >> 5, lane = t & 31;
    int node = blockIdx.x * 8 + warp;
    if (node >= n) return;

    float4 f = *(const float4*)(feat + (size_t)node * FIN + lane * 4);
    float4 f2 = make_float4(f.x * f.x, f.y * f.y, f.z * f.z, f.w * f.w);
    float accl[4], accr[4];
#pragma unroll
    for (int h = 0; h < 4; h++) {
        const float* a = wl + h * FIN + lane * 4;
        const float* b = wr + h * FIN + lane * 4;
        accl[h] = f2.x * a[0] + f2.y * a[1] + f2.z * a[2] + f2.w * a[3];
        accr[h] = f2.x * b[0] + f2.y * b[1] + f2.z * b[2] + f2.w * b[3];
    }
#pragma unroll
    for (int off = 16; off; off >>= 1) {
#pragma unroll
        for (int h = 0; h < 4; h++) {
            accl[h] += __shfl_xor_sync(0xffffffffu, accl[h], off);
            accr[h] += __shfl_xor_sync(0xffffffffu, accr[h], off);
        }
    }
    if (lane < 4) {
        int idx = node * 4 + lane;
        d_el2[idx]   = sel4(accl, lane);
        d_er2[idx]   = sel4(accr, lane);
        d_m[idx]     = 0u;      // < fOrd(anything)
        d_denom[idx] = 0.0f;
    }
}

// ---- K1: ft = feat @ fc_w^T  (SIMT tiled, 32 rows/block, 1 col/thread) ----
__global__ void k1_gemm(const float* __restrict__ feat, const float* __restrict__ fcw, int n) {
    __shared__ float fS[32 * FIN];  // 16 KB
    int t = threadIdx.x;            // 256
    int m0 = blockIdx.x * 32;
#pragma unroll
    for (int i = 0; i < 4; i++) {
        int idx = t + i * 256;          // float4 index 0..1023
        int row = idx >> 5;             // 32 float4 per row
        int col = (idx & 31) * 4;
        float4 v = make_float4(0.f, 0.f, 0.f, 0.f);
        if (m0 + row < n) v = *(const float4*)(feat + (size_t)(m0 + row) * FIN + col);
        *(float4*)(fS + row * FIN + col) = v;
    }
    __syncthreads();

    float acc[32];
#pragma unroll
    for (int i = 0; i < 32; i++) acc[i] = 0.f;
    int j = t;  // output column 0..255

#pragma unroll
    for (int kc = 0; kc < FIN; kc += 32) {
        float wreg[32];
#pragma unroll
        for (int i = 0; i < 8; i++) {
            float4 w4 = *(const float4*)(fcw + (size_t)j * FIN + kc + i * 4);
            wreg[i * 4 + 0] = w4.x; wreg[i * 4 + 1] = w4.y;
            wreg[i * 4 + 2] = w4.z; wreg[i * 4 + 3] = w4.w;
        }
#pragma unroll
        for (int kk = 0; kk < 32; kk += 4) {
#pragma unroll
            for (int i = 0; i < 32; i++) {
                float4 f4 = *(const float4*)(fS + i * FIN + kc + kk);
                acc[i] += f4.x * wreg[kk] + f4.y * wreg[kk + 1]
                        + f4.z * wreg[kk + 2] + f4.w * wreg[kk + 3];
            }
        }
    }
#pragma unroll
    for (int i = 0; i < 32; i++)
        if (m0 + i < n) d_ft[(size_t)(m0 + i) * HF + j] = acc[i];
}

// ---- K3: edge scores + atomic max. One warp per edge. ----
__global__ void k3_edge(const float* __restrict__ feat, const int* __restrict__ src,
                        const int* __restrict__ dst, int eN) {
    __shared__ float ws[NHEAD * FIN];
    int t = threadIdx.x;
    ws[t] = d_w[t]; ws[t + 256] = d_w[t + 256];
    __syncthreads();
    int warp = t >> 5, lane = t & 31;
    int e = blockIdx.x * 8 + warp;
    if (e >= eN) return;
    int s = src[e], d = dst[e];

    float4 fs = *(const float4*)(feat + (size_t)s * FIN + lane * 4);
    float4 fd = *(const float4*)(feat + (size_t)d * FIN + lane * 4);
    float4 p = make_float4(fs.x * fd.x, fs.y * fd.y, fs.z * fd.z, fs.w * fd.w);

    float acc[4];
#pragma unroll
    for (int h = 0; h < 4; h++) {
        const float* w4 = ws + h * FIN + lane * 4;
        acc[h] = p.x * w4[0] + p.y * w4[1] + p.z * w4[2] + p.w * w4[3];
    }
#pragma unroll
    for (int off = 16; off; off >>= 1) {
#pragma unroll
        for (int h = 0; h < 4; h++)
            acc[h] += __shfl_xor_sync(0xffffffffu, acc[h], off);
    }
    if (lane < 4) {
        float v = sel4(acc, lane) + d_el2[s * 4 + lane] + d_er2[d * 4 + lane];
        d_e[(size_t)e * 4 + lane] = v;
        atomicMax(&d_m[d * 4 + lane], fOrd(v));
    }
}

// ---- K4: exp + denom + unnormalized aggregation. One warp per edge. ----
__global__ void k4_agg(const int* __restrict__ src, const int* __restrict__ dst,
                       float* __restrict__ out, int eN) {
    int t = threadIdx.x, warp = t >> 5, lane = t & 31;
    int e = blockIdx.x * 8 + warp;
    if (e >= eN) return;
    int s = src[e], d = dst[e];

    float ex = 0.f;
    if (lane < 4) {
        float ev = d_e[(size_t)e * 4 + lane];
        float mh = fUnord(d_m[d * 4 + lane]);
        ex = expf(ev - mh);
        atomicAdd(&d_denom[d * 4 + lane], ex);
    }
    float exl = __shfl_sync(0xffffffffu, ex, lane >> 3);  // head = lane/8

    const float4* fp = (const float4*)(d_ft + (size_t)s * HF + lane * 8);
    float4 a = fp[0], b = fp[1];
    a.x *= exl; a.y *= exl; a.z *= exl; a.w *= exl;
    b.x *= exl; b.y *= exl; b.z *= exl; b.w *= exl;

    float* op = out + (size_t)d * HF + lane * 8;
    asm volatile("red.global.add.v4.f32 [%0], {%1,%2,%3,%4};"
                 :: "l"(op), "f"(a.x), "f"(a.y), "f"(a.z), "f"(a.w) : "memory");
    asm volatile("red.global.add.v4.f32 [%0], {%1,%2,%3,%4};"
                 :: "l"(op + 4), "f"(b.x), "f"(b.y), "f"(b.z), "f"(b.w) : "memory");
}

// ---- K5: normalize + bias ----
__global__ void k5_final(float* __restrict__ out, const float* __restrict__ bias, int n) {
    int idx = blockIdx.x * blockDim.x + threadIdx.x;
    if (idx >= n * HF) return;
    int h = (idx >> 6) & 3;
    int node = idx >> 8;
    float dn = d_denom[node * 4 + h];
    float v = out[idx];
    out[idx] = (dn > 0.f ? v / dn : 0.f) + bias[idx & 255];
}

extern "C" void kernel_launch(void* const* d_in, const int* in_sizes, int n_in,
                              void* d_out, int out_size) {
    const float* feat = (const float*)d_in[0];
    const int*   src  = (const int*)d_in[1];
    const int*   dst  = (const int*)d_in[2];
    const float* fcw  = (const float*)d_in[3];
    const float* al   = (const float*)d_in[4];
    const float* ar   = (const float*)d_in[5];
    const float* al1  = (const float*)d_in[6];
    const float* ar1  = (const float*)d_in[7];
    const float* bias = (const float*)d_in[8];
    float* out = (float*)d_out;

    int n = in_sizes[0] / FIN;
    int e = in_sizes[1];

    k0_prep<<<1, 512>>>(al, ar, al1, ar1);
    kzero<<<(n * HF / 4 + 255) / 256, 256>>>((float4*)out, n * HF / 4);
    k2_node<<<(n + 7) / 8, 256>>>(feat, n);
    k1_gemm<<<(n + 31) / 32, 256>>>(feat, fcw, n);
    k3_edge<<<(e + 7) / 8, 256>>>(feat, src, dst, e);
    k4_agg<<<(e + 7) / 8, 256>>>(src, dst, out, e);
    k5_final<<<(n * HF + 255) / 256, 256>>>(out, bias, n);
}

// round 2
// speedup vs baseline: 1.1709x; 1.1709x over previous
#include <cuda_runtime.h>
#include <math_constants.h>

#define NMAX 50000
#define EMAX 800000
#define FIN 128
#define NHEAD 4
#define HF 256   // NHEAD * F_OUT

// ---- scratch (device globals; no allocation allowed) ----
__device__ float d_ft[NMAX * HF];        // projected features [N,256]
__device__ float d_e[EMAX * NHEAD];      // edge scores, CSR (dst-sorted) order
__device__ int   d_ssrc[EMAX];           // src id, CSR order
__device__ int   d_deg[NMAX];            // degree histogram
__device__ int   d_off[NMAX + 1];        // CSR offsets
__device__ int   d_cur[NMAX];            // scatter cursors
__device__ int   d_bsum[256];            // scan block sums
__device__ int   d_bpre[256];            // scan block prefixes
__device__ float d_el2[NMAX * NHEAD];
__device__ float d_er2[NMAX * NHEAD];
__device__ float d_w[NHEAD * FIN];       // al*ar - 2*al1*ar1
__device__ float d_wl1[NHEAD * FIN];     // al1^2
__device__ float d_wr1[NHEAD * FIN];     // ar1^2

__device__ __forceinline__ float sel4(const float a[4], int l) {
    return l == 0 ? a[0] : l == 1 ? a[1] : l == 2 ? a[2] : a[3];
}

// packed f32x2 helpers (FFMA2 — only reachable via PTX)
__device__ __forceinline__ unsigned long long pk2(float lo, float hi) {
    unsigned long long r;
    asm("mov.b64 %0, {%1,%2};" : "=l"(r) : "f"(lo), "f"(hi));
    return r;
}
__device__ __forceinline__ void upk2(unsigned long long v, float& lo, float& hi) {
    asm("mov.b64 {%0,%1}, %2;" : "=f"(lo), "=f"(hi) : "l"(v));
}
__device__ __forceinline__ void ffma2(unsigned long long& d, unsigned long long a,
                                      unsigned long long b) {
    asm("fma.rn.f32x2 %0, %1, %2, %0;" : "+l"(d) : "l"(a), "l"(b));
}

// ---- K0: combine attention vectors ----
__global__ void k0_prep(const float* __restrict__ al, const float* __restrict__ ar,
                        const float* __restrict__ al1, const float* __restrict__ ar1) {
    int i = threadIdx.x;  // 512 threads
    d_w[i]   = al[i] * ar[i] - 2.0f * al1[i] * ar1[i];
    d_wl1[i] = al1[i] * al1[i];
    d_wr1[i] = ar1[i] * ar1[i];
}

// ---- zero degree histogram ----
__global__ void kz_deg(int n) {
    int i = blockIdx.x * blockDim.x + threadIdx.x;
    if (i < n) d_deg[i] = 0;
}

// ---- histogram of dst ----
__global__ void khist(const int* __restrict__ dst, int e) {
    int i = blockIdx.x * blockDim.x + threadIdx.x;
    if (i < e) atomicAdd(&d_deg[dst[i]], 1);
}

// ---- scan A: per-block sums of 256 degrees ----
__global__ void kscanA(int n) {
    __shared__ int sh[256];
    int t = threadIdx.x;
    int i = blockIdx.x * 256 + t;
    sh[t] = (i < n) ? d_deg[i] : 0;
    __syncthreads();
#pragma unroll
    for (int off = 128; off; off >>= 1) {
        if (t < off) sh[t] += sh[t + off];
        __syncthreads();
    }
    if (t == 0) d_bsum[blockIdx.x] = sh[0];
}

// ---- scan B: exclusive scan of block sums (nb <= 256) ----
__global__ void kscanB(int nb, int n, int e) {
    __shared__ int sh[256];
    int t = threadIdx.x;
    sh[t] = (t < nb) ? d_bsum[t] : 0;
    __syncthreads();
#pragma unroll
    for (int off = 1; off < 256; off <<= 1) {
        int x = (t >= off) ? sh[t - off] : 0;
        __syncthreads();
        sh[t] += x;
        __syncthreads();
    }
    if (t < nb) d_bpre[t] = (t ? sh[t - 1] : 0);
    if (t == 0) d_off[n] = e;
}

// ---- scan C: per-block exclusive scan + prefix -> offsets ----
__global__ void kscanC(int n) {
    __shared__ int sh[256];
    int t = threadIdx.x;
    int i = blockIdx.x * 256 + t;
    int v = (i < n) ? d_deg[i] : 0;
    sh[t] = v;
    __syncthreads();
#pragma unroll
    for (int off = 1; off < 256; off <<= 1) {
        int x = (t >= off) ? sh[t - off] : 0;
        __syncthreads();
        sh[t] += x;
        __syncthreads();
    }
    if (i < n) {
        int o = d_bpre[blockIdx.x] + sh[t] - v;  // exclusive
        d_off[i] = o;
        d_cur[i] = o;
    }
}

// ---- K2: per-node el2/er2. One warp per node. ----
__global__ void k2_node(const float* __restrict__ feat, int n) {
    __shared__ float wl[NHEAD * FIN], wr[NHEAD * FIN];
    int t = threadIdx.x;
    wl[t] = d_wl1[t]; wl[t + 256] = d_wl1[t + 256];
    wr[t] = d_wr1[t]; wr[t + 256] = d_wr1[t + 256];
    __syncthreads();
    int warp = t >> 5, lane = t & 31;
    int node = blockIdx.x * 8 + warp;
    if (node >= n) return;

    float4 f = *(const float4*)(feat + (size_t)node * FIN + lane * 4);
    float4 f2 = make_float4(f.x * f.x, f.y * f.y, f.z * f.z, f.w * f.w);
    float accl[4], accr[4];
#pragma unroll
    for (int h = 0; h < 4; h++) {
        const float* a = wl + h * FIN + lane * 4;
        const float* b = wr + h * FIN + lane * 4;
        accl[h] = f2.x * a[0] + f2.y * a[1] + f2.z * a[2] + f2.w * a[3];
        accr[h] = f2.x * b[0] + f2.y * b[1] + f2.z * b[2] + f2.w * b[3];
    }
#pragma unroll
    for (int off = 16; off; off >>= 1) {
#pragma unroll
        for (int h = 0; h < 4; h++) {
            accl[h] += __shfl_xor_sync(0xffffffffu, accl[h], off);
            accr[h] += __shfl_xor_sync(0xffffffffu, accr[h], off);
        }
    }
    if (lane < 4) {
        int idx = node * 4 + lane;
        d_el2[idx] = sel4(accl, lane);
        d_er2[idx] = sel4(accr, lane);
    }
}

// ---- K1: ft = feat @ fc_w^T. 64x256 block tile, 8x8 thread tile, FFMA2. ----
__global__ void __launch_bounds__(256) k1_gemm(const float* __restrict__ feat,
                                               const float* __restrict__ fcw, int n) {
    __shared__ float As[64 * 16];    // 4 KB
    __shared__ float Bs[16 * 256];   // 16 KB
    int t = threadIdx.x;
    int tx = t & 31, ty = t >> 5;    // col group 0..31, row group 0..7
    int m0 = blockIdx.x * 64;

    unsigned long long acc2[8][4];
#pragma unroll
    for (int i = 0; i < 8; i++)
#pragma unroll
        for (int j = 0; j < 4; j++) acc2[i][j] = 0ull;

    int arow = t >> 2, akq = (t & 3) * 4;  // A load: row 0..63, float4 slot

#pragma unroll
    for (int kc = 0; kc < FIN; kc += 16) {
        // load A tile: 64 rows x 16 k
        float4 av = make_float4(0.f, 0.f, 0.f, 0.f);
        if (m0 + arow < n)
            av = *(const float4*)(feat + (size_t)(m0 + arow) * FIN + kc + akq);
        *(float4*)(As + arow * 16 + akq) = av;
        // load B tile: 16 k x 256 j (transpose of fcw[j][k])
#pragma unroll
        for (int q = 0; q < 4; q++) {
            float4 w4 = *(const float4*)(fcw + (size_t)t * FIN + kc + q * 4);
            Bs[(q * 4 + 0) * 256 + t] = w4.x;
            Bs[(q * 4 + 1) * 256 + t] = w4.y;
            Bs[(q * 4 + 2) * 256 + t] = w4.z;
            Bs[(q * 4 + 3) * 256 + t] = w4.w;
        }
        __syncthreads();

#pragma unroll
        for (int k = 0; k < 16; k++) {
            float4 b0 = *(float4*)&Bs[k * 256 + tx * 8];
            float4 b1 = *(float4*)&Bs[k * 256 + tx * 8 + 4];
            unsigned long long bb0 = pk2(b0.x, b0.y), bb1 = pk2(b0.z, b0.w);
            unsigned long long bb2 = pk2(b1.x, b1.y), bb3 = pk2(b1.z, b1.w);
#pragma unroll
            for (int i = 0; i < 8; i++) {
                float a = As[(ty * 8 + i) * 16 + k];
                unsigned long long aa = pk2(a, a);
                ffma2(acc2[i][0], aa, bb0);
                ffma2(acc2[i][1], aa, bb1);
                ffma2(acc2[i][2], aa, bb2);
                ffma2(acc2[i][3], aa, bb3);
            }
        }
        __syncthreads();
    }

#pragma unroll
    for (int i = 0; i < 8; i++) {
        int row = m0 + ty * 8 + i;
        if (row < n) {
            float4 v0, v1;
            upk2(acc2[i][0], v0.x, v0.y); upk2(acc2[i][1], v0.z, v0.w);
            upk2(acc2[i][2], v1.x, v1.y); upk2(acc2[i][3], v1.z, v1.w);
            float* o = d_ft + (size_t)row * HF + tx * 8;
            *(float4*)o = v0;
            *(float4*)(o + 4) = v1;
        }
    }
}

// ---- K3: edge scores + scatter into CSR. One warp per edge. ----
__global__ void k3_edge(const float* __restrict__ feat, const int* __restrict__ src,
                        const int* __restrict__ dst, int eN) {
    __shared__ float ws[NHEAD * FIN];
    int t = threadIdx.x;
    ws[t] = d_w[t]; ws[t + 256] = d_w[t + 256];
    __syncthreads();
    int warp = t >> 5, lane = t & 31;
    int e = blockIdx.x * 8 + warp;
    if (e >= eN) return;
    int s = src[e], d = dst[e];

    float4 fs = *(const float4*)(feat + (size_t)s * FIN + lane * 4);
    float4 fd = *(const float4*)(feat + (size_t)d * FIN + lane * 4);
    float4 p = make_float4(fs.x * fd.x, fs.y * fd.y, fs.z * fd.z, fs.w * fd.w);

    float acc[4];
#pragma unroll
    for (int h = 0; h < 4; h++) {
        const float* w4 = ws + h * FIN + lane * 4;
        acc[h] = p.x * w4[0] + p.y * w4[1] + p.z * w4[2] + p.w * w4[3];
    }
#pragma unroll
    for (int off = 16; off; off >>= 1) {
#pragma unroll
        for (int h = 0; h < 4; h++)
            acc[h] += __shfl_xor_sync(0xffffffffu, acc[h], off);
    }
    int pos = 0;
    if (lane == 0) pos = atomicAdd(&d_cur[d], 1);
    pos = __shfl_sync(0xffffffffu, pos, 0);
    if (lane < 4)
        d_e[(size_t)pos * 4 + lane] = sel4(acc, lane) + d_el2[s * 4 + lane] + d_er2[d * 4 + lane];
    if (lane == 0) d_ssrc[pos] = s;
}

// ---- K4: per-dst softmax + aggregation. One block per node. ----
__global__ void __launch_bounds__(256) k4_node(float* __restrict__ out,
                                               const float* __restrict__ bias) {
    __shared__ float sh_m[4], sh_inv[4];
    int node = blockIdx.x;
    int t = threadIdx.x;
    int st = d_off[node];
    int deg = d_off[node + 1] - st;

    if (deg == 0) {  // uniform branch per block
        out[(size_t)node * HF + t] = bias[t];
        return;
    }

    int warp = t >> 5, lane = t & 31;
    if (warp < 4) {  // softmax stats: warp = head
        float mx = -CUDART_INF_F;
        for (int i = lane; i < deg; i += 32)
            mx = fmaxf(mx, d_e[(size_t)(st + i) * 4 + warp]);
#pragma unroll
        for (int off = 16; off; off >>= 1)
            mx = fmaxf(mx, __shfl_xor_sync(0xffffffffu, mx, off));
        float sm = 0.f;
        for (int i = lane; i < deg; i += 32)
            sm += __expf(d_e[(size_t)(st + i) * 4 + warp] - mx);
#pragma unroll
        for (int off = 16; off; off >>= 1)
            sm += __shfl_xor_sync(0xffffffffu, sm, off);
        if (lane == 0) { sh_m[warp] = mx; sh_inv[warp] = 1.0f / sm; }
    }
    __syncthreads();

    int h = t >> 6;
    float mh = sh_m[h], inv = sh_inv[h];
    float acc = 0.f;
#pragma unroll 4
    for (int i = 0; i < deg; i++) {
        int s = d_ssrc[st + i];
        float wv = __expf(d_e[(size_t)(st + i) * 4 + h] - mh);
        acc = fmaf(wv, d_ft[(size_t)s * HF + t], acc);
    }
    out[(size_t)node * HF + t] = acc * inv + bias[t];
}

extern "C" void kernel_launch(void* const* d_in, const int* in_sizes, int n_in,
                              void* d_out, int out_size) {
    const float* feat = (const float*)d_in[0];
    const int*   src  = (const int*)d_in[1];
    const int*   dst  = (const int*)d_in[2];
    const float* fcw  = (const float*)d_in[3];
    const float* al   = (const float*)d_in[4];
    const float* ar   = (const float*)d_in[5];
    const float* al1  = (const float*)d_in[6];
    const float* ar1  = (const float*)d_in[7];
    const float* bias = (const float*)d_in[8];
    float* out = (float*)d_out;

    int n = in_sizes[0] / FIN;
    int e = in_sizes[1];
    int nb = (n + 255) / 256;

    kz_deg<<<nb, 256>>>(n);
    k0_prep<<<1, 512>>>(al, ar, al1, ar1);
    khist<<<(e + 255) / 256, 256>>>(dst, e);
    kscanA<<<nb, 256>>>(n);
    kscanB<<<1, 256>>>(nb, n, e);
    kscanC<<<nb, 256>>>(n);
    k2_node<<<(n + 7) / 8, 256>>>(feat, n);
    k1_gemm<<<(n + 63) / 64, 256>>>(feat, fcw, n);
    k3_edge<<<(e + 7) / 8, 256>>>(feat, src, dst, e);
    k4_node<<<n, 256>>>(out, bias);
}

// round 3
// speedup vs baseline: 1.3118x; 1.1204x over previous
#include <cuda_runtime.h>
#include <math_constants.h>

#define NMAX 50000
#define EMAX 800000
#define FIN 128
#define NHEAD 4
#define HF 256   // NHEAD * F_OUT

// ---- scratch (device globals; no allocation allowed) ----
__device__ float d_ft[NMAX * HF];          // projected features [N,256]
__device__ float d_e[NHEAD * EMAX];        // edge scores, PLANAR [h][E], CSR order
__device__ int   d_ssrc[EMAX];             // src id, CSR order
__device__ int   d_deg[NMAX];              // degree histogram
__device__ int   d_off[NMAX + 1];          // CSR offsets
__device__ int   d_cur[NMAX];              // scatter cursors
__device__ int   d_bsum[256];              // scan block sums
__device__ int   d_bpre[256];              // scan block prefixes
__device__ float d_el2[NMAX * NHEAD];
__device__ float d_er2[NMAX * NHEAD];
__device__ float d_w[NHEAD * FIN];         // al*ar - 2*al1*ar1
__device__ float d_wl1[NHEAD * FIN];       // al1^2
__device__ float d_wr1[NHEAD * FIN];       // ar1^2

__device__ __forceinline__ float sel4(const float a[4], int l) {
    return l == 0 ? a[0] : l == 1 ? a[1] : l == 2 ? a[2] : a[3];
}
__device__ __forceinline__ int sel4i(const int a[4], int l) {
    return l == 0 ? a[0] : l == 1 ? a[1] : l == 2 ? a[2] : a[3];
}

// packed f32x2 helpers (FFMA2 — only reachable via PTX)
__device__ __forceinline__ unsigned long long pk2(float lo, float hi) {
    unsigned long long r;
    asm("mov.b64 %0, {%1,%2};" : "=l"(r) : "f"(lo), "f"(hi));
    return r;
}
__device__ __forceinline__ void upk2(unsigned long long v, float& lo, float& hi) {
    asm("mov.b64 {%0,%1}, %2;" : "=f"(lo), "=f"(hi) : "l"(v));
}
__device__ __forceinline__ void ffma2(unsigned long long& d, unsigned long long a,
                                      unsigned long long b) {
    asm("fma.rn.f32x2 %0, %1, %2, %0;" : "+l"(d) : "l"(a), "l"(b));
}

// ---- K0: zero degree histogram + combine attention vectors ----
__global__ void kinit(const float* __restrict__ al, const float* __restrict__ ar,
                      const float* __restrict__ al1, const float* __restrict__ ar1, int n) {
    int i = blockIdx.x * 256 + threadIdx.x;
    if (i < n) d_deg[i] = 0;
    if (i < NHEAD * FIN) {
        d_w[i]   = al[i] * ar[i] - 2.0f * al1[i] * ar1[i];
        d_wl1[i] = al1[i] * al1[i];
        d_wr1[i] = ar1[i] * ar1[i];
    }
}

// ---- histogram of dst ----
__global__ void khist(const int* __restrict__ dst, int e) {
    int i = blockIdx.x * blockDim.x + threadIdx.x;
    if (i < e) atomicAdd(&d_deg[dst[i]], 1);
}

// ---- scan A: per-block sums of 256 degrees ----
__global__ void kscanA(int n) {
    __shared__ int sh[256];
    int t = threadIdx.x;
    int i = blockIdx.x * 256 + t;
    sh[t] = (i < n) ? d_deg[i] : 0;
    __syncthreads();
#pragma unroll
    for (int off = 128; off; off >>= 1) {
        if (t < off) sh[t] += sh[t + off];
        __syncthreads();
    }
    if (t == 0) d_bsum[blockIdx.x] = sh[0];
}

// ---- scan B: exclusive scan of block sums (nb <= 256) ----
__global__ void kscanB(int nb, int n, int e) {
    __shared__ int sh[256];
    int t = threadIdx.x;
    sh[t] = (t < nb) ? d_bsum[t] : 0;
    __syncthreads();
#pragma unroll
    for (int off = 1; off < 256; off <<= 1) {
        int x = (t >= off) ? sh[t - off] : 0;
        __syncthreads();
        sh[t] += x;
        __syncthreads();
    }
    if (t < nb) d_bpre[t] = (t ? sh[t - 1] : 0);
    if (t == 0) d_off[n] = e;
}

// ---- scan C: per-block exclusive scan + prefix -> offsets ----
__global__ void kscanC(int n) {
    __shared__ int sh[256];
    int t = threadIdx.x;
    int i = blockIdx.x * 256 + t;
    int v = (i < n) ? d_deg[i] : 0;
    sh[t] = v;
    __syncthreads();
#pragma unroll
    for (int off = 1; off < 256; off <<= 1) {
        int x = (t >= off) ? sh[t - off] : 0;
        __syncthreads();
        sh[t] += x;
        __syncthreads();
    }
    if (i < n) {
        int o = d_bpre[blockIdx.x] + sh[t] - v;  // exclusive
        d_off[i] = o;
        d_cur[i] = o;
    }
}

// ---- K2: per-node el2/er2. One warp per node. ----
__global__ void k2_node(const float* __restrict__ feat, int n) {
    __shared__ float wl[NHEAD * FIN], wr[NHEAD * FIN];
    int t = threadIdx.x;
    wl[t] = d_wl1[t]; wl[t + 256] = d_wl1[t + 256];
    wr[t] = d_wr1[t]; wr[t + 256] = d_wr1[t + 256];
    __syncthreads();
    int warp = t >> 5, lane = t & 31;
    int node = blockIdx.x * 8 + warp;
    if (node >= n) return;

    float4 f = *(const float4*)(feat + (size_t)node * FIN + lane * 4);
    float4 f2 = make_float4(f.x * f.x, f.y * f.y, f.z * f.z, f.w * f.w);
    float accl[4], accr[4];
#pragma unroll
    for (int h = 0; h < 4; h++) {
        const float* a = wl + h * FIN + lane * 4;
        const float* b = wr + h * FIN + lane * 4;
        accl[h] = f2.x * a[0] + f2.y * a[1] + f2.z * a[2] + f2.w * a[3];
        accr[h] = f2.x * b[0] + f2.y * b[1] + f2.z * b[2] + f2.w * b[3];
    }
#pragma unroll
    for (int off = 16; off; off >>= 1) {
#pragma unroll
        for (int h = 0; h < 4; h++) {
            accl[h] += __shfl_xor_sync(0xffffffffu, accl[h], off);
            accr[h] += __shfl_xor_sync(0xffffffffu, accr[h], off);
        }
    }
    if (lane < 4) {
        int idx = node * 4 + lane;
        d_el2[idx] = sel4(accl, lane);
        d_er2[idx] = sel4(accr, lane);
    }
}

// ---- K1: ft = feat @ fc_w^T. 64x256 block tile, 8x8 thread tile, FFMA2. ----
__global__ void __launch_bounds__(256) k1_gemm(const float* __restrict__ feat,
                                               const float* __restrict__ fcw, int n) {
    __shared__ float As[64 * 16];    // 4 KB
    __shared__ float Bs[16 * 256];   // 16 KB
    int t = threadIdx.x;
    int tx = t & 31, ty = t >> 5;
    int m0 = blockIdx.x * 64;

    unsigned long long acc2[8][4];
#pragma unroll
    for (int i = 0; i < 8; i++)
#pragma unroll
        for (int j = 0; j < 4; j++) acc2[i][j] = 0ull;

    int arow = t >> 2, akq = (t & 3) * 4;

#pragma unroll
    for (int kc = 0; kc < FIN; kc += 16) {
        float4 av = make_float4(0.f, 0.f, 0.f, 0.f);
        if (m0 + arow < n)
            av = *(const float4*)(feat + (size_t)(m0 + arow) * FIN + kc + akq);
        *(float4*)(As + arow * 16 + akq) = av;
#pragma unroll
        for (int q = 0; q < 4; q++) {
            float4 w4 = *(const float4*)(fcw + (size_t)t * FIN + kc + q * 4);
            Bs[(q * 4 + 0) * 256 + t] = w4.x;
            Bs[(q * 4 + 1) * 256 + t] = w4.y;
            Bs[(q * 4 + 2) * 256 + t] = w4.z;
            Bs[(q * 4 + 3) * 256 + t] = w4.w;
        }
        __syncthreads();

#pragma unroll
        for (int k = 0; k < 16; k++) {
            float4 b0 = *(float4*)&Bs[k * 256 + tx * 8];
            float4 b1 = *(float4*)&Bs[k * 256 + tx * 8 + 4];
            unsigned long long bb0 = pk2(b0.x, b0.y), bb1 = pk2(b0.z, b0.w);
            unsigned long long bb2 = pk2(b1.x, b1.y), bb3 = pk2(b1.z, b1.w);
#pragma unroll
            for (int i = 0; i < 8; i++) {
                float a = As[(ty * 8 + i) * 16 + k];
                unsigned long long aa = pk2(a, a);
                ffma2(acc2[i][0], aa, bb0);
                ffma2(acc2[i][1], aa, bb1);
                ffma2(acc2[i][2], aa, bb2);
                ffma2(acc2[i][3], aa, bb3);
            }
        }
        __syncthreads();
    }

#pragma unroll
    for (int i = 0; i < 8; i++) {
        int row = m0 + ty * 8 + i;
        if (row < n) {
            float4 v0, v1;
            upk2(acc2[i][0], v0.x, v0.y); upk2(acc2[i][1], v0.z, v0.w);
            upk2(acc2[i][2], v1.x, v1.y); upk2(acc2[i][3], v1.z, v1.w);
            float* o = d_ft + (size_t)row * HF + tx * 8;
            *(float4*)o = v0;
            *(float4*)(o + 4) = v1;
        }
    }
}

// ---- K3: edge scores + scatter into CSR. 4 edges per warp for ILP. ----
__global__ void __launch_bounds__(256) k3_edge(const float* __restrict__ feat,
                                               const int* __restrict__ src,
                                               const int* __restrict__ dst, int eN) {
    __shared__ float ws[NHEAD * FIN];
    int t = threadIdx.x;
    ws[t] = d_w[t]; ws[t + 256] = d_w[t + 256];
    __syncthreads();
    int warp = t >> 5, lane = t & 31;
    int e0 = (blockIdx.x * 8 + warp) * 4;

    int s[4], d[4];
    bool valid[4];
#pragma unroll
    for (int q = 0; q < 4; q++) {
        int e = e0 + q;
        valid[q] = e < eN;
        s[q] = valid[q] ? src[e] : 0;
        d[q] = valid[q] ? dst[e] : 0;
    }

    float acc[4][4];
#pragma unroll
    for (int q = 0; q < 4; q++) {
        float4 fs = *(const float4*)(feat + (size_t)s[q] * FIN + lane * 4);
        float4 fd = *(const float4*)(feat + (size_t)d[q] * FIN + lane * 4);
        float4 p = make_float4(fs.x * fd.x, fs.y * fd.y, fs.z * fd.z, fs.w * fd.w);
#pragma unroll
        for (int h = 0; h < 4; h++) {
            const float* w4 = ws + h * FIN + lane * 4;
            acc[q][h] = p.x * w4[0] + p.y * w4[1] + p.z * w4[2] + p.w * w4[3];
        }
    }
#pragma unroll
    for (int off = 16; off; off >>= 1)
#pragma unroll
        for (int q = 0; q < 4; q++)
#pragma unroll
            for (int h = 0; h < 4; h++)
                acc[q][h] += __shfl_xor_sync(0xffffffffu, acc[q][h], off);

    // lanes 0..3 each grab the CSR slot for edge q=lane (one atomic instruction)
    int pos = 0;
    if (lane < 4 && valid[lane])
        pos = atomicAdd(&d_cur[sel4i(d, lane)], 1);
    if (lane < 4 && valid[lane])
        d_ssrc[pos] = sel4i(s, lane);

#pragma unroll
    for (int q = 0; q < 4; q++) {
        if (!valid[q]) break;
        int pq = __shfl_sync(0xffffffffu, pos, q);
        if (lane < 4) {
            float v = acc[q][0];
            v = sel4(acc[q], lane);
            v += d_el2[s[q] * 4 + lane] + d_er2[d[q] * 4 + lane];
            d_e[(size_t)lane * EMAX + pq] = v;   // planar [h][E]
        }
    }
}

// ---- K4: per-dst softmax + aggregation, smem-staged for MLP. 1 block/node. ----
__global__ void __launch_bounds__(256) k4_node(float* __restrict__ out,
                                               const float* __restrict__ bias) {
    __shared__ int   srcSm[64];
    __shared__ float alphaSm[256];   // [h][64]
    __shared__ float sh_m[4], sh_inv[4];
    int node = blockIdx.x;
    int t = threadIdx.x;
    int st = d_off[node];
    int deg = d_off[node + 1] - st;

    if (deg == 0) {
        out[(size_t)node * HF + t] = bias[t];
        return;
    }

    int warp = t >> 5, lane = t & 31;
    if (warp < 4) {  // softmax stats: warp = head, planar coalesced reads
        const float* ep = d_e + (size_t)warp * EMAX + st;
        float mx = -CUDART_INF_F;
        for (int i = lane; i < deg; i += 32) mx = fmaxf(mx, ep[i]);
#pragma unroll
        for (int off = 16; off; off >>= 1)
            mx = fmaxf(mx, __shfl_xor_sync(0xffffffffu, mx, off));
        float sm = 0.f;
        for (int i = lane; i < deg; i += 32) sm += __expf(ep[i] - mx);
#pragma unroll
        for (int off = 16; off; off >>= 1)
            sm += __shfl_xor_sync(0xffffffffu, sm, off);
        if (lane == 0) { sh_m[warp] = mx; sh_inv[warp] = 1.0f / sm; }
    }
    __syncthreads();

    int h = t >> 6;
    int i64 = t & 63;
    float mh = sh_m[h], inv = sh_inv[h];
    float acc = 0.f;

    for (int c0 = 0; c0 < deg; c0 += 64) {
        int cd = min(64, deg - c0);
        if (t < cd) srcSm[t] = d_ssrc[st + c0 + t];
        if (i64 < cd)
            alphaSm[t] = __expf(d_e[(size_t)h * EMAX + st + c0 + i64] - mh) * inv;
        __syncthreads();
#pragma unroll 4
        for (int i = 0; i < cd; i++) {
            int s = srcSm[i];
            acc = fmaf(alphaSm[(h << 6) | i], d_ft[(size_t)s * HF + t], acc);
        }
        __syncthreads();
    }
    out[(size_t)node * HF + t] = acc + bias[t];
}

extern "C" void kernel_launch(void* const* d_in, const int* in_sizes, int n_in,
                              void* d_out, int out_size) {
    const float* feat = (const float*)d_in[0];
    const int*   src  = (const int*)d_in[1];
    const int*   dst  = (const int*)d_in[2];
    const float* fcw  = (const float*)d_in[3];
    const float* al   = (const float*)d_in[4];
    const float* ar   = (const float*)d_in[5];
    const float* al1  = (const float*)d_in[6];
    const float* ar1  = (const float*)d_in[7];
    const float* bias = (const float*)d_in[8];
    float* out = (float*)d_out;

    int n = in_sizes[0] / FIN;
    int e = in_sizes[1];
    int nb = (n + 255) / 256;

    kinit<<<nb, 256>>>(al, ar, al1, ar1, n);
    khist<<<(e + 255) / 256, 256>>>(dst, e);
    kscanA<<<nb, 256>>>(n);
    kscanB<<<1, 256>>>(nb, n, e);
    kscanC<<<nb, 256>>>(n);
    k2_node<<<(n + 7) / 8, 256>>>(feat, n);
    k1_gemm<<<(n + 63) / 64, 256>>>(feat, fcw, n);
    k3_edge<<<(e + 31) / 32, 256>>>(feat, src, dst, e);
    k4_node<<<n, 256>>>(out, bias);
}